// round 10
// baseline (speedup 1.0000x reference)
#include <cuda_runtime.h>

#define B_  64
#define L_  200
#define NS_ 1000
#define D_  128
#define M_  50
#define BL_ (B_*L_)
#define WSTR 64   // padded w-row stride (slots 50..63 zero)

typedef unsigned long long u64;

// -------- scratch (device globals; no allocation allowed) --------
__device__ float g_eWT[D_*D_];        // e_W transposed [k][d]
__device__ float g_aWT[D_*D_];        // a_W transposed
__device__ float g_frT[D_*D_];        // read-half of f_W transposed [k][d]
__device__ float g_fkT[D_*D_];        // k-half of f_W transposed
__device__ float g_wtab[1024*WSTR];   // softmax weights per skill (padded)
__device__ float g_etab[2048*D_];     // sigmoid erase per x (rows>=2000 junk)
__device__ float g_atab[2048*D_];     // tanh add per x
__device__ float g_kftab[1024*D_];    // k_emb[s] @ f_Wk^T (no bias/act)
__device__ float g_read[BL_*D_];      // read vectors

__device__ __forceinline__ float fsigmoid(float x){ return 1.f/(1.f+__expf(-x)); }
__device__ __forceinline__ float ftanh(float x){ float y; asm("tanh.approx.f32 %0, %1;":"=f"(y):"f"(x)); return y; }

// ---- packed fp32x2 helpers (sm_100+) ----
__device__ __forceinline__ u64 pk2(float x){
    u64 r; asm("mov.b64 %0, {%1, %1};" : "=l"(r) : "r"(__float_as_uint(x))); return r;
}
__device__ __forceinline__ u64 pk22(float lo, float hi){
    u64 r; asm("mov.b64 %0, {%1, %2};" : "=l"(r) : "r"(__float_as_uint(lo)), "r"(__float_as_uint(hi))); return r;
}
__device__ __forceinline__ void fma2(u64& d, u64 a, u64 b){
    asm("fma.rn.f32x2 %0, %1, %2, %0;" : "+l"(d) : "l"(a), "l"(b));
}
__device__ __forceinline__ void unpk(u64 v, float& lo, float& hi){
    unsigned int a, b; asm("mov.b64 {%0, %1}, %2;" : "=r"(a), "=r"(b) : "l"(v));
    lo = __uint_as_float(a); hi = __uint_as_float(b);
}

// =====================================================================
// Kernel 0: transpose the 4 weight matrices once (tiled, conflict-free).
// =====================================================================
extern "C" __global__ void __launch_bounds__(256)
k0_transpose(const float* __restrict__ e_W, const float* __restrict__ a_W,
             const float* __restrict__ f_W)
{
    __shared__ float tile[32][33];
    const int m  = blockIdx.y;
    const int tb = blockIdx.x;
    const int d0 = (tb & 3) * 32;
    const int k0 = (tb >> 2) * 32;
    const int c  = threadIdx.x & 31;
    const int rb = threadIdx.x >> 5;

    const float* src; int stride, off; float* dst;
    if      (m == 0) { src = e_W; stride = D_;   off = 0;   dst = g_eWT; }
    else if (m == 1) { src = a_W; stride = D_;   off = 0;   dst = g_aWT; }
    else if (m == 2) { src = f_W; stride = 2*D_; off = 0;   dst = g_frT; }
    else             { src = f_W; stride = 2*D_; off = D_;  dst = g_fkT; }

    #pragma unroll
    for (int p = 0; p < 4; p++) {
        int r = rb + p*8;
        tile[r][c] = src[(size_t)(d0 + r)*stride + off + k0 + c];
    }
    __syncthreads();
    #pragma unroll
    for (int p = 0; p < 4; p++) {
        int r = rb + p*8;
        dst[(size_t)(k0 + r)*D_ + d0 + c] = tile[c][r];
    }
}

// =====================================================================
// Kernel A: build all tables. 56 blocks x 512 threads, 128KB smem.
//   [0,16)  e-table  : 128 rows/block, 8x(2xf32x2) register tile
//   [16,32) a-table  [32,40) kf-table  [40,56) w-table (softmax, 64 rows)
// =====================================================================
extern "C" __global__ void __launch_bounds__(512)
kA_tables(const float* __restrict__ k_emb, const float* __restrict__ v_emb,
          const float* __restrict__ Mk,
          const float* __restrict__ e_b, const float* __restrict__ a_b)
{
    extern __shared__ float sm[];
    float* sx = sm;                 // up to 128*128 activation tile (64KB)
    float* sw = sm + 128*D_;        // 128*128 transposed weights (64KB)
    const int tid = threadIdx.x;
    const int tx = tid & 31, ty = tid >> 5;   // ty 0..15
    const int c0 = tx * 4;
    const int bid = blockIdx.x;

    if (bid < 40) {
        // ------- e/a/kf tables: 128-row GEMM, packed f32x2 -------
        const int type  = (bid < 16) ? 0 : (bid < 32) ? 1 : 2;
        const int rbase = (type == 0 ? bid : type == 1 ? bid - 16 : bid - 32) * 128;
        const float* WT = (type == 0) ? g_eWT : (type == 1) ? g_aWT : g_fkT;
        const float* xs = (type == 2) ? k_emb : v_emb;
        const int rmax  = (type == 2) ? NS_ - 1 : 2*NS_ - 1;
        const int r0 = ty * 8;

        {   // stage transposed weights (4096 f4)
            float4* sw4 = (float4*)sw;
            const float4* WT4 = (const float4*)WT;
            #pragma unroll
            for (int i = 0; i < 8; i++) sw4[tid + i*512] = __ldg(&WT4[tid + i*512]);
        }
        {   // gather 128 activation rows (4096 f4)
            float4* s4 = (float4*)sx;
            const float4* xs4 = (const float4*)xs;
            #pragma unroll
            for (int i = 0; i < 8; i++) {
                int u = tid + i*512;
                int r = u >> 5, cc = u & 31;
                int rr = min(rbase + r, rmax);
                s4[u] = __ldg(&xs4[(size_t)rr*32 + cc]);
            }
        }
        __syncthreads();

        u64 acc2[8][2] = {};
        const float4* s4 = (const float4*)sx;
        #pragma unroll 2
        for (int k4 = 0; k4 < 32; k4++) {
            float4 vr[8];
            #pragma unroll
            for (int i = 0; i < 8; i++) vr[i] = s4[(r0+i)*32 + k4];
            #pragma unroll
            for (int s = 0; s < 4; s++) {
                int k = 4*k4 + s;
                ulonglong2 wv = *(const ulonglong2*)&sw[k*D_ + c0];
                #pragma unroll
                for (int i = 0; i < 8; i++) {
                    u64 v2 = pk2(((const float*)&vr[i])[s]);
                    fma2(acc2[i][0], v2, wv.x);
                    fma2(acc2[i][1], v2, wv.y);
                }
            }
        }
        #pragma unroll
        for (int i = 0; i < 8; i++) {
            int row = rbase + r0 + i;
            float a0, a1, a2, a3;
            unpk(acc2[i][0], a0, a1);
            unpk(acc2[i][1], a2, a3);
            float4 o;
            if (type == 0) {
                float4 bb = *(const float4*)&e_b[c0];
                o.x = fsigmoid(a0 + bb.x); o.y = fsigmoid(a1 + bb.y);
                o.z = fsigmoid(a2 + bb.z); o.w = fsigmoid(a3 + bb.w);
                *(float4*)&g_etab[(size_t)row*D_ + c0] = o;
            } else if (type == 1) {
                float4 bb = *(const float4*)&a_b[c0];
                o.x = ftanh(a0 + bb.x); o.y = ftanh(a1 + bb.y);
                o.z = ftanh(a2 + bb.z); o.w = ftanh(a3 + bb.w);
                *(float4*)&g_atab[(size_t)row*D_ + c0] = o;
            } else {
                o.x = a0; o.y = a1; o.z = a2; o.w = a3;
                *(float4*)&g_kftab[(size_t)row*D_ + c0] = o;
            }
        }
    } else {
        // ---------------- w (softmax) table, 64 rows, packed (m0,m1) ----------------
        const int rbase = (bid - 40) * 64;
        const int r0 = ty * 4;
        float* MkT = sw;                      // 128*65 (pad 65: conflict-free)
        for (int i = tid; i < M_*D_; i += 512) {
            int m = i >> 7, k = i & 127;
            MkT[k*65 + m] = Mk[i];
        }
        for (int i = tid; i < D_*14; i += 512) {
            int k = i / 14, m = 50 + (i % 14);
            MkT[k*65 + m] = 0.f;
        }
        {
            float4* s4 = (float4*)sx;
            const float4* ke4 = (const float4*)k_emb;
            #pragma unroll
            for (int i = 0; i < 4; i++) {
                int u = tid + i*512;
                int r = u >> 5, cc = u & 31;
                int rr = min(rbase + r, NS_ - 1);
                s4[u] = __ldg(&ke4[(size_t)rr*32 + cc]);
            }
        }
        __syncthreads();

        const int m0 = tx, m1 = tx + 32;
        u64 acc2[4] = {};
        const float4* s4 = (const float4*)sx;
        #pragma unroll 2
        for (int k4 = 0; k4 < 32; k4++) {
            float4 kr[4];
            #pragma unroll
            for (int i = 0; i < 4; i++) kr[i] = s4[(r0+i)*32 + k4];
            #pragma unroll
            for (int s = 0; s < 4; s++) {
                int k = 4*k4 + s;
                u64 mk2 = pk22(MkT[k*65 + m0], MkT[k*65 + m1]);
                #pragma unroll
                for (int i = 0; i < 4; i++) {
                    u64 k2 = pk2(((const float*)&kr[i])[s]);
                    fma2(acc2[i], k2, mk2);
                }
            }
        }
        #pragma unroll
        for (int i = 0; i < 4; i++) {
            float v0, v1raw;
            unpk(acc2[i], v0, v1raw);
            float v1 = (m1 < M_) ? v1raw : -1e30f;
            float mx = fmaxf(v0, v1);
            #pragma unroll
            for (int o = 16; o >= 1; o >>= 1) mx = fmaxf(mx, __shfl_xor_sync(0xffffffffu, mx, o));
            float e0 = __expf(v0 - mx);
            float e1 = (m1 < M_) ? __expf(v1 - mx) : 0.f;
            float s = e0 + e1;
            #pragma unroll
            for (int o = 16; o >= 1; o >>= 1) s += __shfl_xor_sync(0xffffffffu, s, o);
            float inv = __frcp_rn(s);
            int row = rbase + r0 + i;
            g_wtab[row*WSTR + m0] = e0 * inv;
            g_wtab[row*WSTR + m1] = e1 * inv;   // zero in pad region
        }
    }
}

// =====================================================================
// Kernel B: sequential scan; grid (B, 2 d-halves) x 512 threads.
// Contiguous 8-slot m-ownership (pairs packed as f32x2); all w/e/a
// staged to smem up front; 154KB -> 1 block/SM.
// =====================================================================
extern "C" __global__ void __launch_bounds__(512)
kB_scan(const int* __restrict__ skills, const int* __restrict__ responses,
        const float* __restrict__ Mv0)
{
    extern __shared__ float sb[];
    float* s_w = sb;               // L*64
    float* s_e = sb + L_*64;       // L*64 (this block's 64-d slice)
    float* s_a = sb + 2*L_*64;     // L*64
    __shared__ int s_x[L_], s_sk[L_];

    const int b   = blockIdx.x;
    const int tid = threadIdx.x;
    const int dhalf = blockIdx.y;        // 0 or 1

    for (int t = tid; t < L_; t += 512) {
        int sk = skills[b*L_ + t];
        int r  = responses[b*L_ + t];
        int mr = (r > -1) ? r : 0;
        s_sk[t] = sk;
        s_x[t]  = sk + NS_ * mr;
    }
    __syncthreads();

    {   // bulk stage: 16 float4 per t per table
        float4* sw4 = (float4*)s_w;
        float4* se4 = (float4*)s_e;
        float4* sa4 = (float4*)s_a;
        const float4* wt4 = (const float4*)g_wtab;
        const float4* et4 = (const float4*)g_etab;
        const float4* at4 = (const float4*)g_atab;
        const int dbase4 = dhalf * 16;
        for (int u = tid; u < L_*16; u += 512) {
            int t = u >> 4, c = u & 15;
            int xx = s_x[t], kk = s_sk[t];
            sw4[u] = __ldg(&wt4[kk*16 + c]);
            se4[u] = __ldg(&et4[(size_t)xx*32 + dbase4 + c]);
            sa4[u] = __ldg(&at4[(size_t)xx*32 + dbase4 + c]);
        }
    }
    __syncthreads();

    const int mg  = tid & 7;
    const int dl  = tid >> 3;
    const int d   = dhalf * 64 + dl;
    const int mbase = mg * 8;

    u64 mv2[4];
    #pragma unroll
    for (int j = 0; j < 4; j++) {
        int m = mbase + 2*j;
        float lo = (m     < M_) ? Mv0[m*D_ + d]       : 0.f;
        float hi = (m + 1 < M_) ? Mv0[(m + 1)*D_ + d] : 0.f;
        mv2[j] = pk22(lo, hi);
    }

    float* rp = g_read + (size_t)b*L_*D_ + d;

    #pragma unroll 2
    for (int t = 0; t < L_; t++) {
        float ev = s_e[t*64 + dl];
        float av = s_a[t*64 + dl];
        u64 nev2 = pk2(-ev);
        u64 av2  = pk2(av);
        const ulonglong2* wp = (const ulonglong2*)&s_w[t*64 + mbase];
        ulonglong2 wA = wp[0], wB = wp[1];
        u64 w2[4] = {wA.x, wA.y, wB.x, wB.y};

        u64 rd0 = 0ull, rd1 = 0ull;
        #pragma unroll
        for (int j = 0; j < 4; j++) {
            if (j & 1) fma2(rd1, w2[j], mv2[j]);
            else       fma2(rd0, w2[j], mv2[j]);       // read uses PRE-update Mv
            u64 g2 = av2;
            fma2(g2, nev2, mv2[j]);                    // g = a - e*mv
            fma2(mv2[j], w2[j], g2);                   // mv += w*g  (w==0 pad: no-op)
        }
        float r0l, r0h, r1l, r1h;
        unpk(rd0, r0l, r0h);
        unpk(rd1, r1l, r1h);
        float rd = (r0l + r0h) + (r1l + r1h);
        rd += __shfl_xor_sync(0xffffffffu, rd, 1);
        rd += __shfl_xor_sync(0xffffffffu, rd, 2);
        rd += __shfl_xor_sync(0xffffffffu, rd, 4);
        if (mg == 0) rp[t*D_] = rd;
    }
}

// =====================================================================
// Kernel C: f = tanh(read @ f_Wr^T + kf_tab[skill] + f_b); p = sigmoid(f.p_W+p_b)
// 128 blocks x 640 threads, 100 rows/block (5-row x 2xf32x2 tile).
// =====================================================================
extern "C" __global__ void __launch_bounds__(640)
kC_out(const int* __restrict__ skills,
       const float* __restrict__ f_b,
       const float* __restrict__ p_W, const float* __restrict__ p_b,
       float* __restrict__ out)
{
    extern __shared__ float sm[];
    float* hx  = sm;                 // 100*128 read tile (50KB)
    float* fWT = sm + 100*D_;        // 128*128 transposed weights (64KB)
    __shared__ int s_sk[100];

    const int tid  = threadIdx.x;
    const int row0 = blockIdx.x * 100;

    if (tid < 100) s_sk[tid] = skills[row0 + tid];
    {
        float4* w4 = (float4*)fWT;
        const float4* WT4 = (const float4*)g_frT;
        for (int u = tid; u < 4096; u += 640) w4[u] = __ldg(&WT4[u]);
    }
    {
        float4* h4 = (float4*)hx;
        const float4* rd4 = (const float4*)g_read;
        for (int u = tid; u < 100*32; u += 640) h4[u] = __ldg(&rd4[(size_t)row0*32 + u]);
    }
    __syncthreads();

    const int tx = tid & 31, ty = tid >> 5;   // ty 0..19
    const int r0 = ty * 5, c0 = tx * 4;

    u64 acc2[5][2] = {};
    const float4* h4 = (const float4*)hx;
    #pragma unroll 2
    for (int k4 = 0; k4 < 32; k4++) {
        float4 hr[5];
        #pragma unroll
        for (int i = 0; i < 5; i++) hr[i] = h4[(r0+i)*32 + k4];
        #pragma unroll
        for (int s = 0; s < 4; s++) {
            int k = k4*4 + s;
            ulonglong2 wv = *(const ulonglong2*)&fWT[k*D_ + c0];
            #pragma unroll
            for (int i = 0; i < 5; i++) {
                u64 v2 = pk2(((const float*)&hr[i])[s]);
                fma2(acc2[i][0], v2, wv.x);
                fma2(acc2[i][1], v2, wv.y);
            }
        }
    }
    float4 fb = *(const float4*)&f_b[c0];
    float4 pw = *(const float4*)&p_W[c0];
    float pb = p_b[0];
    #pragma unroll
    for (int i = 0; i < 5; i++) {
        int row = row0 + r0 + i;
        int sk = s_sk[r0 + i];
        float4 kf = *(const float4*)&g_kftab[(size_t)sk*D_ + c0];
        float a0, a1, a2, a3;
        unpk(acc2[i][0], a0, a1);
        unpk(acc2[i][1], a2, a3);
        float f0 = ftanh(a0 + kf.x + fb.x);
        float f1 = ftanh(a1 + kf.y + fb.y);
        float f2 = ftanh(a2 + kf.z + fb.z);
        float f3 = ftanh(a3 + kf.w + fb.w);
        float pp = f0*pw.x + f1*pw.y + f2*pw.z + f3*pw.w;
        #pragma unroll
        for (int o = 16; o >= 1; o >>= 1) pp += __shfl_xor_sync(0xffffffffu, pp, o);
        if (tx == 0) {
            int bb = row / L_, t = row % L_;
            if (t >= 1) out[bb*(L_-1) + (t-1)] = fsigmoid(pp + pb);
        }
    }
}

// =====================================================================
extern "C" void kernel_launch(void* const* d_in, const int* in_sizes, int n_in,
                              void* d_out, int out_size)
{
    const int*   skills    = (const int*)  d_in[0];
    const int*   responses = (const int*)  d_in[1];
    const float* k_emb     = (const float*)d_in[2];
    const float* v_emb     = (const float*)d_in[3];
    const float* Mk        = (const float*)d_in[4];
    const float* Mv0       = (const float*)d_in[5];
    const float* e_W       = (const float*)d_in[6];
    const float* e_b       = (const float*)d_in[7];
    const float* a_W       = (const float*)d_in[8];
    const float* a_b       = (const float*)d_in[9];
    const float* f_W       = (const float*)d_in[10];
    const float* f_b       = (const float*)d_in[11];
    const float* p_W       = (const float*)d_in[12];
    const float* p_b       = (const float*)d_in[13];
    float* out = (float*)d_out;

    const size_t SZA = (size_t)(128*D_ + D_*D_) * sizeof(float);   // 131072
    const size_t SZB = (size_t)(3*L_*64) * sizeof(float);          // 153600
    const size_t SZC = (size_t)(100*D_ + D_*D_) * sizeof(float);   // 116736

    cudaFuncSetAttribute(kA_tables, cudaFuncAttributeMaxDynamicSharedMemorySize, (int)SZA);
    cudaFuncSetAttribute(kB_scan,   cudaFuncAttributeMaxDynamicSharedMemorySize, (int)SZB);
    cudaFuncSetAttribute(kC_out,    cudaFuncAttributeMaxDynamicSharedMemorySize, (int)SZC);

    k0_transpose<<<dim3(16, 4), 256>>>(e_W, a_W, f_W);
    kA_tables<<<56, 512, SZA>>>(k_emb, v_emb, Mk, e_b, a_b);
    kB_scan<<<dim3(B_, 2), 512, SZB>>>(skills, responses, Mv0);
    kC_out<<<128, 640, SZC>>>(skills, f_b, p_W, p_b, out);
}

// round 11
// speedup vs baseline: 1.2687x; 1.2687x over previous
#include <cuda_runtime.h>

#define B_  64
#define L_  200
#define NS_ 1000
#define D_  128
#define M_  50
#define BL_ (B_*L_)
#define WSTR 64   // padded w-row stride (slots 50..63 zero)

// -------- scratch (device globals; no allocation allowed) --------
__device__ float g_eWT[D_*D_];        // e_W transposed [k][d]
__device__ float g_aWT[D_*D_];        // a_W transposed
__device__ float g_frT[D_*D_];        // read-half of f_W transposed [k][d]
__device__ float g_fkT[D_*D_];        // k-half of f_W transposed
__device__ float g_wtab[1024*WSTR];   // softmax weights per skill (padded)
__device__ float g_etab[2048*D_];     // sigmoid erase per x (rows>=2000 junk)
__device__ float g_atab[2048*D_];     // tanh add per x
__device__ float g_kftab[1024*D_];    // k_emb[s] @ f_Wk^T + f_b
__device__ float g_read[BL_*D_];      // read vectors

__device__ __forceinline__ float fsigmoid(float x){ return 1.f/(1.f+__expf(-x)); }
__device__ __forceinline__ float ftanh(float x){ float y; asm("tanh.approx.f32 %0, %1;":"=f"(y):"f"(x)); return y; }
__device__ __forceinline__ unsigned tf32r(float x){
    unsigned r; asm("cvt.rna.tf32.f32 %0, %1;" : "=r"(r) : "f"(x)); return r;
}
__device__ __forceinline__ void mma8(float* c,
        unsigned a0, unsigned a1, unsigned a2, unsigned a3,
        unsigned b0, unsigned b1){
    asm("mma.sync.aligned.m16n8k8.row.col.f32.tf32.tf32.f32 "
        "{%0,%1,%2,%3}, {%4,%5,%6,%7}, {%8,%9}, {%0,%1,%2,%3};"
        : "+f"(c[0]), "+f"(c[1]), "+f"(c[2]), "+f"(c[3])
        : "r"(a0), "r"(a1), "r"(a2), "r"(a3), "r"(b0), "r"(b1));
}

// =====================================================================
// Kernel 0: transpose the 4 weight matrices once (tiled, conflict-free).
// =====================================================================
extern "C" __global__ void __launch_bounds__(256)
k0_transpose(const float* __restrict__ e_W, const float* __restrict__ a_W,
             const float* __restrict__ f_W)
{
    __shared__ float tile[32][33];
    const int m  = blockIdx.y;
    const int tb = blockIdx.x;
    const int d0 = (tb & 3) * 32;
    const int k0 = (tb >> 2) * 32;
    const int c  = threadIdx.x & 31;
    const int rb = threadIdx.x >> 5;

    const float* src; int stride, off; float* dst;
    if      (m == 0) { src = e_W; stride = D_;   off = 0;   dst = g_eWT; }
    else if (m == 1) { src = a_W; stride = D_;   off = 0;   dst = g_aWT; }
    else if (m == 2) { src = f_W; stride = 2*D_; off = 0;   dst = g_frT; }
    else             { src = f_W; stride = 2*D_; off = D_;  dst = g_fkT; }

    #pragma unroll
    for (int p = 0; p < 4; p++) {
        int r = rb + p*8;
        tile[r][c] = src[(size_t)(d0 + r)*stride + off + k0 + c];
    }
    __syncthreads();
    #pragma unroll
    for (int p = 0; p < 4; p++) {
        int r = rb + p*8;
        dst[(size_t)(k0 + r)*D_ + d0 + c] = tile[c][r];
    }
}

// =====================================================================
// Kernel A: build all tables. 56 blocks x 512 threads, 128KB smem.
//   [0,16)  e-table  : 128 rows/block (2048 rows), 8x4 register tile
//   [16,32) a-table  [32,40) kf-table (+f_b)  [40,56) w-table (softmax)
// =====================================================================
extern "C" __global__ void __launch_bounds__(512)
kA_tables(const float* __restrict__ k_emb, const float* __restrict__ v_emb,
          const float* __restrict__ Mk,
          const float* __restrict__ e_b, const float* __restrict__ a_b,
          const float* __restrict__ f_b)
{
    extern __shared__ float sm[];
    float* sx = sm;                 // up to 128*128 activation tile (64KB)
    float* sw = sm + 128*D_;        // 128*128 transposed weights (64KB)
    const int tid = threadIdx.x;
    const int tx = tid & 31, ty = tid >> 5;   // ty 0..15
    const int c0 = tx * 4;
    const int bid = blockIdx.x;

    if (bid < 40) {
        // ------- e/a/kf tables: 128-row GEMM, 8x4 tile -------
        const int type  = (bid < 16) ? 0 : (bid < 32) ? 1 : 2;
        const int rbase = (type == 0 ? bid : type == 1 ? bid - 16 : bid - 32) * 128;
        const float* WT = (type == 0) ? g_eWT : (type == 1) ? g_aWT : g_fkT;
        const float* xs = (type == 2) ? k_emb : v_emb;
        const int rmax  = (type == 2) ? NS_ - 1 : 2*NS_ - 1;
        const int r0 = ty * 8;

        {   // stage transposed weights (4096 f4)
            float4* sw4 = (float4*)sw;
            const float4* WT4 = (const float4*)WT;
            #pragma unroll
            for (int i = 0; i < 8; i++) sw4[tid + i*512] = __ldg(&WT4[tid + i*512]);
        }
        {   // gather 128 activation rows (4096 f4)
            float4* s4 = (float4*)sx;
            const float4* xs4 = (const float4*)xs;
            #pragma unroll
            for (int i = 0; i < 8; i++) {
                int u = tid + i*512;
                int r = u >> 5, cc = u & 31;
                int rr = min(rbase + r, rmax);
                s4[u] = __ldg(&xs4[(size_t)rr*32 + cc]);
            }
        }
        __syncthreads();

        float acc[8][4] = {};
        const float4* s4 = (const float4*)sx;
        #pragma unroll 2
        for (int k4 = 0; k4 < 32; k4++) {
            float4 vr[8];
            #pragma unroll
            for (int i = 0; i < 8; i++) vr[i] = s4[(r0+i)*32 + k4];
            #pragma unroll
            for (int s = 0; s < 4; s++) {
                int k = 4*k4 + s;
                float4 w = *(const float4*)&sw[k*D_ + c0];
                #pragma unroll
                for (int i = 0; i < 8; i++) {
                    float vv = ((const float*)&vr[i])[s];
                    acc[i][0] = fmaf(vv, w.x, acc[i][0]);
                    acc[i][1] = fmaf(vv, w.y, acc[i][1]);
                    acc[i][2] = fmaf(vv, w.z, acc[i][2]);
                    acc[i][3] = fmaf(vv, w.w, acc[i][3]);
                }
            }
        }
        #pragma unroll
        for (int i = 0; i < 8; i++) {
            int row = rbase + r0 + i;
            float4 o;
            if (type == 0) {
                float4 bb = *(const float4*)&e_b[c0];
                o.x = fsigmoid(acc[i][0] + bb.x); o.y = fsigmoid(acc[i][1] + bb.y);
                o.z = fsigmoid(acc[i][2] + bb.z); o.w = fsigmoid(acc[i][3] + bb.w);
                *(float4*)&g_etab[(size_t)row*D_ + c0] = o;
            } else if (type == 1) {
                float4 bb = *(const float4*)&a_b[c0];
                o.x = ftanh(acc[i][0] + bb.x); o.y = ftanh(acc[i][1] + bb.y);
                o.z = ftanh(acc[i][2] + bb.z); o.w = ftanh(acc[i][3] + bb.w);
                *(float4*)&g_atab[(size_t)row*D_ + c0] = o;
            } else {
                float4 bb = *(const float4*)&f_b[c0];   // fold f_b here
                o.x = acc[i][0] + bb.x; o.y = acc[i][1] + bb.y;
                o.z = acc[i][2] + bb.z; o.w = acc[i][3] + bb.w;
                *(float4*)&g_kftab[(size_t)row*D_ + c0] = o;
            }
        }
    } else {
        // ---------------- w (softmax) table, 64 rows ----------------
        const int rbase = (bid - 40) * 64;
        const int r0 = ty * 4;
        float* MkT = sw;                      // 128*65 (pad 65: conflict-free)
        for (int i = tid; i < M_*D_; i += 512) {
            int m = i >> 7, k = i & 127;
            MkT[k*65 + m] = Mk[i];
        }
        for (int i = tid; i < D_*14; i += 512) {
            int k = i / 14, m = 50 + (i % 14);
            MkT[k*65 + m] = 0.f;
        }
        {
            float4* s4 = (float4*)sx;
            const float4* ke4 = (const float4*)k_emb;
            #pragma unroll
            for (int i = 0; i < 4; i++) {
                int u = tid + i*512;
                int r = u >> 5, cc = u & 31;
                int rr = min(rbase + r, NS_ - 1);
                s4[u] = __ldg(&ke4[(size_t)rr*32 + cc]);
            }
        }
        __syncthreads();

        const int m0 = tx, m1 = tx + 32;
        float a0[4] = {}, a1[4] = {};
        const float4* s4 = (const float4*)sx;
        #pragma unroll 4
        for (int k4 = 0; k4 < 32; k4++) {
            float4 kr[4];
            #pragma unroll
            for (int i = 0; i < 4; i++) kr[i] = s4[(r0+i)*32 + k4];
            #pragma unroll
            for (int s = 0; s < 4; s++) {
                int k = 4*k4 + s;
                float mv0 = MkT[k*65 + m0];
                float mv1 = MkT[k*65 + m1];
                #pragma unroll
                for (int i = 0; i < 4; i++) {
                    float kv = ((const float*)&kr[i])[s];
                    a0[i] = fmaf(kv, mv0, a0[i]);
                    a1[i] = fmaf(kv, mv1, a1[i]);
                }
            }
        }
        #pragma unroll
        for (int i = 0; i < 4; i++) {
            float v0 = a0[i];
            float v1 = (m1 < M_) ? a1[i] : -1e30f;
            float mx = fmaxf(v0, v1);
            #pragma unroll
            for (int o = 16; o >= 1; o >>= 1) mx = fmaxf(mx, __shfl_xor_sync(0xffffffffu, mx, o));
            float e0 = __expf(v0 - mx);
            float e1 = (m1 < M_) ? __expf(v1 - mx) : 0.f;
            float s = e0 + e1;
            #pragma unroll
            for (int o = 16; o >= 1; o >>= 1) s += __shfl_xor_sync(0xffffffffu, s, o);
            float inv = __frcp_rn(s);
            int row = rbase + r0 + i;
            g_wtab[row*WSTR + m0] = e0 * inv;
            g_wtab[row*WSTR + m1] = e1 * inv;   // zero in pad region
        }
    }
}

// =====================================================================
// Kernel B: sequential scan; grid (B, 2 d-halves) x 512 threads.
// Strided m-ownership (7 slots/thread); w/e/a staged to smem up front.
// =====================================================================
extern "C" __global__ void __launch_bounds__(512)
kB_scan(const int* __restrict__ skills, const int* __restrict__ responses,
        const float* __restrict__ Mv0)
{
    extern __shared__ float sb[];
    float* s_w = sb;               // L*64
    float* s_e = sb + L_*64;       // L*64 (this block's 64-d slice)
    float* s_a = sb + 2*L_*64;     // L*64
    __shared__ int s_x[L_], s_sk[L_];

    const int b   = blockIdx.x;
    const int tid = threadIdx.x;
    const int dhalf = blockIdx.y;        // 0 or 1

    for (int t = tid; t < L_; t += 512) {
        int sk = skills[b*L_ + t];
        int r  = responses[b*L_ + t];
        int mr = (r > -1) ? r : 0;
        s_sk[t] = sk;
        s_x[t]  = sk + NS_ * mr;
    }
    __syncthreads();

    {   // bulk stage: 16 float4 per t per table
        float4* sw4 = (float4*)s_w;
        float4* se4 = (float4*)s_e;
        float4* sa4 = (float4*)s_a;
        const float4* wt4 = (const float4*)g_wtab;
        const float4* et4 = (const float4*)g_etab;
        const float4* at4 = (const float4*)g_atab;
        const int dbase4 = dhalf * 16;
        for (int u = tid; u < L_*16; u += 512) {
            int t = u >> 4, c = u & 15;
            int xx = s_x[t], kk = s_sk[t];
            sw4[u] = __ldg(&wt4[kk*16 + c]);
            se4[u] = __ldg(&et4[(size_t)xx*32 + dbase4 + c]);
            sa4[u] = __ldg(&at4[(size_t)xx*32 + dbase4 + c]);
        }
    }
    __syncthreads();

    const int mg  = tid & 7;
    const int dl  = tid >> 3;
    const int d   = dhalf * 64 + dl;

    float mv[7];
    #pragma unroll
    for (int j = 0; j < 7; j++) {
        int m = mg + 8*j;
        mv[j] = (m < M_) ? Mv0[m*D_ + d] : 0.f;
    }

    float* rp = g_read + (size_t)b*L_*D_ + d;

    #pragma unroll 2
    for (int t = 0; t < L_; t++) {
        float ev = s_e[t*64 + dl];
        float av = s_a[t*64 + dl];
        const float* wrow = &s_w[t*64 + mg];

        float rda = 0.f, rdb = 0.f;
        #pragma unroll
        for (int j = 0; j < 7; j++) {
            float w = wrow[8*j];                 // broadcast-friendly scalar LDS
            float r_ = fmaf(w, mv[j], 0.f);
            if (j & 1) rdb += r_; else rda += r_;
            float g = fmaf(-ev, mv[j], av);      // a - e*mv
            mv[j] = fmaf(w, g, mv[j]);           // mv += w*(a - e*mv)
        }
        float rd = rda + rdb;
        rd += __shfl_xor_sync(0xffffffffu, rd, 1);
        rd += __shfl_xor_sync(0xffffffffu, rd, 2);
        rd += __shfl_xor_sync(0xffffffffu, rd, 4);
        if (mg == 0) rp[t*D_] = rd;
    }
}

// =====================================================================
// Kernel C: tf32 tensor-core GEMM.  f = tanh(read @ f_Wr^T + kftab[sk]);
// p = sigmoid(f . p_W + p_b).  100 blocks x 256 threads (8 warps),
// 128 rows/block.  A: hA[128][132] (pad 132), B: hB[128][136] k-major.
// mma.sync m16n8k8 tf32; warp w owns rows 16w..16w+15, all 128 cols.
// =====================================================================
extern "C" __global__ void __launch_bounds__(256)
kC_out(const int* __restrict__ skills,
       const float* __restrict__ p_W, const float* __restrict__ p_b,
       float* __restrict__ out)
{
    extern __shared__ float sm[];
    float* hA = sm;                  // 128*132 floats (tf32-rounded read rows)
    float* hB = sm + 128*132;        // 128*136 floats (tf32-rounded frT, k-major)
    __shared__ int s_sk[128];

    const int tid  = threadIdx.x;
    const int row0 = blockIdx.x * 128;

    if (tid < 128) s_sk[tid] = skills[row0 + tid];
    {   // stage A
        const float4* rd4 = (const float4*)g_read;
        #pragma unroll
        for (int i = 0; i < 16; i++) {
            int u = tid + i*256;
            int r = u >> 5, c = u & 31;
            float4 v = __ldg(&rd4[(size_t)row0*32 + u]);
            v.x = __uint_as_float(tf32r(v.x)); v.y = __uint_as_float(tf32r(v.y));
            v.z = __uint_as_float(tf32r(v.z)); v.w = __uint_as_float(tf32r(v.w));
            *(float4*)&hA[r*132 + c*4] = v;
        }
    }
    {   // stage B (g_frT is [k][n], n contiguous)
        const float4* wt4 = (const float4*)g_frT;
        #pragma unroll
        for (int i = 0; i < 16; i++) {
            int u = tid + i*256;
            int k = u >> 5, c = u & 31;
            float4 v = __ldg(&wt4[u]);
            v.x = __uint_as_float(tf32r(v.x)); v.y = __uint_as_float(tf32r(v.y));
            v.z = __uint_as_float(tf32r(v.z)); v.w = __uint_as_float(tf32r(v.w));
            *(float4*)&hB[k*136 + c*4] = v;
        }
    }
    __syncthreads();

    const int wid = tid >> 5, lane = tid & 31;
    const int g = lane >> 2, t = lane & 3;
    const int rw = wid * 16;

    float acc[16][4];
    #pragma unroll
    for (int nt = 0; nt < 16; nt++)
        #pragma unroll
        for (int j = 0; j < 4; j++) acc[nt][j] = 0.f;

    const float* Abase = hA + (rw + g)*132 + t;
    #pragma unroll 4
    for (int kk = 0; kk < 16; kk++) {
        const int k0 = kk*8;
        unsigned a0 = __float_as_uint(Abase[k0]);
        unsigned a1 = __float_as_uint(Abase[k0 + 8*132]);
        unsigned a2 = __float_as_uint(Abase[k0 + 4]);
        unsigned a3 = __float_as_uint(Abase[k0 + 8*132 + 4]);
        const float* B0 = hB + (k0 + t)*136 + g;
        const float* B1 = B0 + 4*136;
        #pragma unroll
        for (int nt = 0; nt < 16; nt++) {
            unsigned b0 = __float_as_uint(B0[nt*8]);
            unsigned b1 = __float_as_uint(B1[nt*8]);
            mma8(acc[nt], a0, a1, a2, a3, b0, b1);
        }
    }

    // epilogue: rows r_lo = rw+g, r_hi = rw+g+8; this thread holds cols
    // {nt*8 + 2t, nt*8 + 2t + 1} for both rows.
    const int rlo = rw + g, rhi = rlo + 8;
    const int sk0 = s_sk[rlo], sk1 = s_sk[rhi];
    const float* kf0p = &g_kftab[(size_t)sk0*D_];
    const float* kf1p = &g_kftab[(size_t)sk1*D_];
    float pp0 = 0.f, pp1 = 0.f;
    #pragma unroll
    for (int nt = 0; nt < 16; nt++) {
        #pragma unroll
        for (int j = 0; j < 2; j++) {
            int col = nt*8 + 2*t + j;
            float pw = __ldg(&p_W[col]);
            pp0 += ftanh(acc[nt][j]     + __ldg(kf0p + col)) * pw;
            pp1 += ftanh(acc[nt][2 + j] + __ldg(kf1p + col)) * pw;
        }
    }
    pp0 += __shfl_xor_sync(0xffffffffu, pp0, 1);
    pp0 += __shfl_xor_sync(0xffffffffu, pp0, 2);
    pp1 += __shfl_xor_sync(0xffffffffu, pp1, 1);
    pp1 += __shfl_xor_sync(0xffffffffu, pp1, 2);
    if (t == 0) {
        float pb = p_b[0];
        int row = row0 + rlo;
        int bb = row / L_, tt = row % L_;
        if (tt >= 1) out[bb*(L_-1) + (tt-1)] = fsigmoid(pp0 + pb);
        row = row0 + rhi;
        bb = row / L_; tt = row % L_;
        if (tt >= 1) out[bb*(L_-1) + (tt-1)] = fsigmoid(pp1 + pb);
    }
}

// =====================================================================
extern "C" void kernel_launch(void* const* d_in, const int* in_sizes, int n_in,
                              void* d_out, int out_size)
{
    const int*   skills    = (const int*)  d_in[0];
    const int*   responses = (const int*)  d_in[1];
    const float* k_emb     = (const float*)d_in[2];
    const float* v_emb     = (const float*)d_in[3];
    const float* Mk        = (const float*)d_in[4];
    const float* Mv0       = (const float*)d_in[5];
    const float* e_W       = (const float*)d_in[6];
    const float* e_b       = (const float*)d_in[7];
    const float* a_W       = (const float*)d_in[8];
    const float* a_b       = (const float*)d_in[9];
    const float* f_W       = (const float*)d_in[10];
    const float* f_b       = (const float*)d_in[11];
    const float* p_W       = (const float*)d_in[12];
    const float* p_b       = (const float*)d_in[13];
    float* out = (float*)d_out;

    const size_t SZA = (size_t)(128*D_ + D_*D_) * sizeof(float);     // 131072
    const size_t SZB = (size_t)(3*L_*64) * sizeof(float);            // 153600
    const size_t SZC = (size_t)(128*132 + 128*136) * sizeof(float);  // 137216

    cudaFuncSetAttribute(kA_tables, cudaFuncAttributeMaxDynamicSharedMemorySize, (int)SZA);
    cudaFuncSetAttribute(kB_scan,   cudaFuncAttributeMaxDynamicSharedMemorySize, (int)SZB);
    cudaFuncSetAttribute(kC_out,    cudaFuncAttributeMaxDynamicSharedMemorySize, (int)SZC);

    k0_transpose<<<dim3(16, 4), 256>>>(e_W, a_W, f_W);
    kA_tables<<<56, 512, SZA>>>(k_emb, v_emb, Mk, e_b, a_b, f_b);
    kB_scan<<<dim3(B_, 2), 512, SZB>>>(skills, responses, Mv0);
    kC_out<<<100, 256, SZC>>>(skills, p_W, p_b, out);
}

// round 12
// speedup vs baseline: 1.5192x; 1.1974x over previous
#include <cuda_runtime.h>

#define B_  64
#define L_  200
#define NS_ 1000
#define D_  128
#define M_  50
#define BL_ (B_*L_)
#define WSTR 64   // padded w-row stride (slots 50..63 zero)

// -------- scratch (device globals; no allocation allowed) --------
__device__ float g_eWT[D_*D_];        // e_W transposed [k][d]
__device__ float g_aWT[D_*D_];        // a_W transposed
__device__ float g_frT[D_*D_];        // read-half of f_W transposed [k][d]
__device__ float g_fkT[D_*D_];        // k-half of f_W transposed
__device__ float g_wtab[1024*WSTR];   // softmax weights per skill (padded)
__device__ float g_etab[2048*D_];     // sigmoid erase per x (rows>=2000 junk)
__device__ float g_atab[2048*D_];     // tanh add per x
__device__ float g_kftab[1024*D_];    // k_emb[s] @ f_Wk^T + f_b
__device__ float g_read[BL_*D_];      // read vectors

__device__ __forceinline__ float fsigmoid(float x){ return 1.f/(1.f+__expf(-x)); }
__device__ __forceinline__ float ftanh(float x){ float y; asm("tanh.approx.f32 %0, %1;":"=f"(y):"f"(x)); return y; }
__device__ __forceinline__ unsigned tf32r(float x){
    unsigned r; asm("cvt.rna.tf32.f32 %0, %1;" : "=r"(r) : "f"(x)); return r;
}
__device__ __forceinline__ void mma8(float* c,
        unsigned a0, unsigned a1, unsigned a2, unsigned a3,
        unsigned b0, unsigned b1){
    asm("mma.sync.aligned.m16n8k8.row.col.f32.tf32.tf32.f32 "
        "{%0,%1,%2,%3}, {%4,%5,%6,%7}, {%8,%9}, {%0,%1,%2,%3};"
        : "+f"(c[0]), "+f"(c[1]), "+f"(c[2]), "+f"(c[3])
        : "r"(a0), "r"(a1), "r"(a2), "r"(a3), "r"(b0), "r"(b1));
}

// =====================================================================
// Kernel 0: transpose the 4 weight matrices once (tiled, conflict-free).
// =====================================================================
extern "C" __global__ void __launch_bounds__(256)
k0_transpose(const float* __restrict__ e_W, const float* __restrict__ a_W,
             const float* __restrict__ f_W)
{
    __shared__ float tile[32][33];
    const int m  = blockIdx.y;
    const int tb = blockIdx.x;
    const int d0 = (tb & 3) * 32;
    const int k0 = (tb >> 2) * 32;
    const int c  = threadIdx.x & 31;
    const int rb = threadIdx.x >> 5;

    const float* src; int stride, off; float* dst;
    if      (m == 0) { src = e_W; stride = D_;   off = 0;   dst = g_eWT; }
    else if (m == 1) { src = a_W; stride = D_;   off = 0;   dst = g_aWT; }
    else if (m == 2) { src = f_W; stride = 2*D_; off = 0;   dst = g_frT; }
    else             { src = f_W; stride = 2*D_; off = D_;  dst = g_fkT; }

    #pragma unroll
    for (int p = 0; p < 4; p++) {
        int r = rb + p*8;
        tile[r][c] = src[(size_t)(d0 + r)*stride + off + k0 + c];
    }
    __syncthreads();
    #pragma unroll
    for (int p = 0; p < 4; p++) {
        int r = rb + p*8;
        dst[(size_t)(k0 + r)*D_ + d0 + c] = tile[c][r];
    }
}

// =====================================================================
// Kernel A: build all tables. 56 blocks x 512 threads, ~137KB smem.
//   [0,16)  e-table  (tf32 mma, 128 rows/block)
//   [16,32) a-table  [32,40) kf-table (+f_b)
//   [40,56) w-table  (softmax, FFMA, 64 rows/block)
// =====================================================================
extern "C" __global__ void __launch_bounds__(512)
kA_tables(const float* __restrict__ k_emb, const float* __restrict__ v_emb,
          const float* __restrict__ Mk,
          const float* __restrict__ e_b, const float* __restrict__ a_b,
          const float* __restrict__ f_b)
{
    extern __shared__ float sm[];
    const int tid = threadIdx.x;
    const int bid = blockIdx.x;

    if (bid < 40) {
        // ------- e/a/kf tables: tf32 mma GEMM, 128 rows/block -------
        float* hA = sm;                  // 128*132 tf32-rounded activations
        float* hB = sm + 128*132;        // 128*136 tf32-rounded weights [k][d]
        const int type  = (bid < 16) ? 0 : (bid < 32) ? 1 : 2;
        const int rbase = (type == 0 ? bid : type == 1 ? bid - 16 : bid - 32) * 128;
        const float* WT = (type == 0) ? g_eWT : (type == 1) ? g_aWT : g_fkT;
        const float* xs = (type == 2) ? k_emb : v_emb;
        const float* bv = (type == 0) ? e_b : (type == 1) ? a_b : f_b;
        const int rmax  = (type == 2) ? NS_ - 1 : 2*NS_ - 1;

        {   // stage A (gathered rows, tf32-rounded)
            const float4* xs4 = (const float4*)xs;
            #pragma unroll
            for (int i = 0; i < 8; i++) {
                int u = tid + i*512;
                int r = u >> 5, c = u & 31;
                int rr = min(rbase + r, rmax);
                float4 v = __ldg(&xs4[(size_t)rr*32 + c]);
                v.x = __uint_as_float(tf32r(v.x)); v.y = __uint_as_float(tf32r(v.y));
                v.z = __uint_as_float(tf32r(v.z)); v.w = __uint_as_float(tf32r(v.w));
                *(float4*)&hA[r*132 + c*4] = v;
            }
        }
        {   // stage B (WT is [k][d], d contiguous)
            const float4* wt4 = (const float4*)WT;
            #pragma unroll
            for (int i = 0; i < 8; i++) {
                int u = tid + i*512;
                int k = u >> 5, c = u & 31;
                float4 v = __ldg(&wt4[u]);
                v.x = __uint_as_float(tf32r(v.x)); v.y = __uint_as_float(tf32r(v.y));
                v.z = __uint_as_float(tf32r(v.z)); v.w = __uint_as_float(tf32r(v.w));
                *(float4*)&hB[k*136 + c*4] = v;
            }
        }
        __syncthreads();

        const int wid = tid >> 5, lane = tid & 31;
        const int g = lane >> 2, t = lane & 3;
        const int stripe = wid >> 1, half = wid & 1;
        const int rw = stripe * 16;

        float acc[8][4];
        #pragma unroll
        for (int n = 0; n < 8; n++)
            #pragma unroll
            for (int j = 0; j < 4; j++) acc[n][j] = 0.f;

        const float* Abase = hA + (rw + g)*132 + t;
        #pragma unroll 4
        for (int kk = 0; kk < 16; kk++) {
            const int k0 = kk*8;
            unsigned a0 = __float_as_uint(Abase[k0]);
            unsigned a1 = __float_as_uint(Abase[k0 + 8*132]);
            unsigned a2 = __float_as_uint(Abase[k0 + 4]);
            unsigned a3 = __float_as_uint(Abase[k0 + 8*132 + 4]);
            const float* B0 = hB + (k0 + t)*136 + g + half*64;
            const float* B1 = B0 + 4*136;
            #pragma unroll
            for (int n = 0; n < 8; n++) {
                unsigned b0 = __float_as_uint(B0[n*8]);
                unsigned b1 = __float_as_uint(B1[n*8]);
                mma8(acc[n], a0, a1, a2, a3, b0, b1);
            }
        }

        const int rlo = rbase + rw + g, rhi = rlo + 8;
        #pragma unroll
        for (int n = 0; n < 8; n++) {
            int c = half*64 + n*8 + 2*t;
            float2 bb = *(const float2*)&bv[c];
            float x0 = acc[n][0] + bb.x, x1 = acc[n][1] + bb.y;
            float y0 = acc[n][2] + bb.x, y1 = acc[n][3] + bb.y;
            float2 lo, hi;
            if (type == 0) {
                lo.x = fsigmoid(x0); lo.y = fsigmoid(x1);
                hi.x = fsigmoid(y0); hi.y = fsigmoid(y1);
                *(float2*)&g_etab[(size_t)rlo*D_ + c] = lo;
                *(float2*)&g_etab[(size_t)rhi*D_ + c] = hi;
            } else if (type == 1) {
                lo.x = ftanh(x0); lo.y = ftanh(x1);
                hi.x = ftanh(y0); hi.y = ftanh(y1);
                *(float2*)&g_atab[(size_t)rlo*D_ + c] = lo;
                *(float2*)&g_atab[(size_t)rhi*D_ + c] = hi;
            } else {
                lo.x = x0; lo.y = x1; hi.x = y0; hi.y = y1;
                *(float2*)&g_kftab[(size_t)rlo*D_ + c] = lo;
                *(float2*)&g_kftab[(size_t)rhi*D_ + c] = hi;
            }
        }
    } else {
        // ---------------- w (softmax) table, 64 rows, FFMA ----------------
        float* sx  = sm;                 // 64*128
        float* MkT = sm + 64*D_;         // 128*65 (pad 65: conflict-free)
        const int rbase = (bid - 40) * 64;
        const int tx = tid & 31, ty = tid >> 5;
        const int r0 = ty * 4;

        for (int i = tid; i < M_*D_; i += 512) {
            int m = i >> 7, k = i & 127;
            MkT[k*65 + m] = Mk[i];
        }
        for (int i = tid; i < D_*14; i += 512) {
            int k = i / 14, m = 50 + (i % 14);
            MkT[k*65 + m] = 0.f;
        }
        {
            float4* s4 = (float4*)sx;
            const float4* ke4 = (const float4*)k_emb;
            #pragma unroll
            for (int i = 0; i < 4; i++) {
                int u = tid + i*512;
                int r = u >> 5, cc = u & 31;
                int rr = min(rbase + r, NS_ - 1);
                s4[u] = __ldg(&ke4[(size_t)rr*32 + cc]);
            }
        }
        __syncthreads();

        const int m0 = tx, m1 = tx + 32;
        float a0[4] = {}, a1[4] = {};
        const float4* s4 = (const float4*)sx;
        #pragma unroll 4
        for (int k4 = 0; k4 < 32; k4++) {
            float4 kr[4];
            #pragma unroll
            for (int i = 0; i < 4; i++) kr[i] = s4[(r0+i)*32 + k4];
            #pragma unroll
            for (int s = 0; s < 4; s++) {
                int k = 4*k4 + s;
                float mv0 = MkT[k*65 + m0];
                float mv1 = MkT[k*65 + m1];
                #pragma unroll
                for (int i = 0; i < 4; i++) {
                    float kv = ((const float*)&kr[i])[s];
                    a0[i] = fmaf(kv, mv0, a0[i]);
                    a1[i] = fmaf(kv, mv1, a1[i]);
                }
            }
        }
        #pragma unroll
        for (int i = 0; i < 4; i++) {
            float v0 = a0[i];
            float v1 = (m1 < M_) ? a1[i] : -1e30f;
            float mx = fmaxf(v0, v1);
            #pragma unroll
            for (int o = 16; o >= 1; o >>= 1) mx = fmaxf(mx, __shfl_xor_sync(0xffffffffu, mx, o));
            float e0 = __expf(v0 - mx);
            float e1 = (m1 < M_) ? __expf(v1 - mx) : 0.f;
            float s = e0 + e1;
            #pragma unroll
            for (int o = 16; o >= 1; o >>= 1) s += __shfl_xor_sync(0xffffffffu, s, o);
            float inv = __frcp_rn(s);
            int row = rbase + r0 + i;
            g_wtab[row*WSTR + m0] = e0 * inv;
            g_wtab[row*WSTR + m1] = e1 * inv;   // zero in pad region
        }
    }
}

// =====================================================================
// Kernel B: sequential scan; grid (B, 2 d-halves) x 512 threads.
// Strided m-ownership (7 slots/thread); w/e/a staged to smem up front.
// =====================================================================
extern "C" __global__ void __launch_bounds__(512)
kB_scan(const int* __restrict__ skills, const int* __restrict__ responses,
        const float* __restrict__ Mv0)
{
    extern __shared__ float sb[];
    float* s_w = sb;               // L*64
    float* s_e = sb + L_*64;       // L*64 (this block's 64-d slice)
    float* s_a = sb + 2*L_*64;     // L*64
    __shared__ int s_x[L_], s_sk[L_];

    const int b   = blockIdx.x;
    const int tid = threadIdx.x;
    const int dhalf = blockIdx.y;        // 0 or 1

    for (int t = tid; t < L_; t += 512) {
        int sk = skills[b*L_ + t];
        int r  = responses[b*L_ + t];
        int mr = (r > -1) ? r : 0;
        s_sk[t] = sk;
        s_x[t]  = sk + NS_ * mr;
    }
    __syncthreads();

    {   // bulk stage: 16 float4 per t per table
        float4* sw4 = (float4*)s_w;
        float4* se4 = (float4*)s_e;
        float4* sa4 = (float4*)s_a;
        const float4* wt4 = (const float4*)g_wtab;
        const float4* et4 = (const float4*)g_etab;
        const float4* at4 = (const float4*)g_atab;
        const int dbase4 = dhalf * 16;
        for (int u = tid; u < L_*16; u += 512) {
            int t = u >> 4, c = u & 15;
            int xx = s_x[t], kk = s_sk[t];
            sw4[u] = __ldg(&wt4[kk*16 + c]);
            se4[u] = __ldg(&et4[(size_t)xx*32 + dbase4 + c]);
            sa4[u] = __ldg(&at4[(size_t)xx*32 + dbase4 + c]);
        }
    }
    __syncthreads();

    const int mg  = tid & 7;
    const int dl  = tid >> 3;
    const int d   = dhalf * 64 + dl;

    float mv[7];
    #pragma unroll
    for (int j = 0; j < 7; j++) {
        int m = mg + 8*j;
        mv[j] = (m < M_) ? Mv0[m*D_ + d] : 0.f;
    }

    float* rp = g_read + (size_t)b*L_*D_ + d;

    #pragma unroll 2
    for (int t = 0; t < L_; t++) {
        float ev = s_e[t*64 + dl];
        float av = s_a[t*64 + dl];
        const float* wrow = &s_w[t*64 + mg];

        float rda = 0.f, rdb = 0.f;
        #pragma unroll
        for (int j = 0; j < 7; j++) {
            float w = wrow[8*j];                 // broadcast-friendly scalar LDS
            float r_ = fmaf(w, mv[j], 0.f);
            if (j & 1) rdb += r_; else rda += r_;
            float g = fmaf(-ev, mv[j], av);      // a - e*mv
            mv[j] = fmaf(w, g, mv[j]);           // mv += w*(a - e*mv)
        }
        float rd = rda + rdb;
        rd += __shfl_xor_sync(0xffffffffu, rd, 1);
        rd += __shfl_xor_sync(0xffffffffu, rd, 2);
        rd += __shfl_xor_sync(0xffffffffu, rd, 4);
        if (mg == 0) rp[t*D_] = rd;
    }
}

// =====================================================================
// Kernel C: tf32 mma GEMM + fused epilogue. 100 blocks x 512 threads.
// 128 rows/block; warp pair (stripe, half) splits the 16 n-tiles.
// After the mainloop the hA region is reused to stage the kf gather
// (coalesced), p_W is staged; cross-half reduction via smem.
// =====================================================================
extern "C" __global__ void __launch_bounds__(512)
kC_out(const int* __restrict__ skills,
       const float* __restrict__ p_W, const float* __restrict__ p_b,
       float* __restrict__ out)
{
    extern __shared__ float sm[];
    float* hA   = sm;                       // 128*132 (A tf32, later kf tile)
    float* hB   = sm + 128*132;             // 128*136 (frT tf32, k-major)
    float* spw  = sm + 128*132 + 128*136;   // 128 (p_W)
    float* sred = spw + 128;                // 256 (row x half partials)
    __shared__ int s_sk[128];

    const int tid  = threadIdx.x;
    const int row0 = blockIdx.x * 128;

    if (tid < 128) { s_sk[tid] = skills[row0 + tid]; spw[tid] = p_W[tid]; }
    {   // stage A
        const float4* rd4 = (const float4*)g_read;
        #pragma unroll
        for (int i = 0; i < 8; i++) {
            int u = tid + i*512;
            int r = u >> 5, c = u & 31;
            float4 v = __ldg(&rd4[(size_t)row0*32 + u]);
            v.x = __uint_as_float(tf32r(v.x)); v.y = __uint_as_float(tf32r(v.y));
            v.z = __uint_as_float(tf32r(v.z)); v.w = __uint_as_float(tf32r(v.w));
            *(float4*)&hA[r*132 + c*4] = v;
        }
    }
    {   // stage B
        const float4* wt4 = (const float4*)g_frT;
        #pragma unroll
        for (int i = 0; i < 8; i++) {
            int u = tid + i*512;
            int k = u >> 5, c = u & 31;
            float4 v = __ldg(&wt4[u]);
            v.x = __uint_as_float(tf32r(v.x)); v.y = __uint_as_float(tf32r(v.y));
            v.z = __uint_as_float(tf32r(v.z)); v.w = __uint_as_float(tf32r(v.w));
            *(float4*)&hB[k*136 + c*4] = v;
        }
    }
    __syncthreads();

    const int wid = tid >> 5, lane = tid & 31;
    const int g = lane >> 2, t = lane & 3;
    const int stripe = wid >> 1, half = wid & 1;
    const int rw = stripe * 16;

    float acc[8][4];
    #pragma unroll
    for (int n = 0; n < 8; n++)
        #pragma unroll
        for (int j = 0; j < 4; j++) acc[n][j] = 0.f;

    const float* Abase = hA + (rw + g)*132 + t;
    #pragma unroll 4
    for (int kk = 0; kk < 16; kk++) {
        const int k0 = kk*8;
        unsigned a0 = __float_as_uint(Abase[k0]);
        unsigned a1 = __float_as_uint(Abase[k0 + 8*132]);
        unsigned a2 = __float_as_uint(Abase[k0 + 4]);
        unsigned a3 = __float_as_uint(Abase[k0 + 8*132 + 4]);
        const float* B0 = hB + (k0 + t)*136 + g + half*64;
        const float* B1 = B0 + 4*136;
        #pragma unroll
        for (int n = 0; n < 8; n++) {
            unsigned b0 = __float_as_uint(B0[n*8]);
            unsigned b1 = __float_as_uint(B1[n*8]);
            mma8(acc[n], a0, a1, a2, a3, b0, b1);
        }
    }
    __syncthreads();                       // all mma reads of hA done

    {   // stage kf tile into hA (coalesced gather; f_b pre-folded)
        const float4* kf4 = (const float4*)g_kftab;
        #pragma unroll
        for (int i = 0; i < 8; i++) {
            int u = tid + i*512;
            int r = u >> 5, c = u & 31;
            *(float4*)&hA[r*132 + c*4] = __ldg(&kf4[(size_t)s_sk[r]*32 + c]);
        }
    }
    __syncthreads();

    const int rloL = rw + g, rhiL = rloL + 8;
    float pp0 = 0.f, pp1 = 0.f;
    #pragma unroll
    for (int n = 0; n < 8; n++) {
        int c = half*64 + n*8 + 2*t;
        float pw0 = spw[c], pw1 = spw[c+1];
        pp0 += ftanh(acc[n][0] + hA[rloL*132 + c    ]) * pw0
             + ftanh(acc[n][1] + hA[rloL*132 + c + 1]) * pw1;
        pp1 += ftanh(acc[n][2] + hA[rhiL*132 + c    ]) * pw0
             + ftanh(acc[n][3] + hA[rhiL*132 + c + 1]) * pw1;
    }
    pp0 += __shfl_xor_sync(0xffffffffu, pp0, 1);
    pp0 += __shfl_xor_sync(0xffffffffu, pp0, 2);
    pp1 += __shfl_xor_sync(0xffffffffu, pp1, 1);
    pp1 += __shfl_xor_sync(0xffffffffu, pp1, 2);
    if (t == 0) {
        sred[rloL*2 + half] = pp0;
        sred[rhiL*2 + half] = pp1;
    }
    __syncthreads();
    if (tid < 128) {
        float pp = sred[tid*2] + sred[tid*2 + 1] + p_b[0];
        int row = row0 + tid;
        int bb = row / L_, tt = row % L_;
        if (tt >= 1) out[bb*(L_-1) + (tt-1)] = fsigmoid(pp);
    }
}

// =====================================================================
extern "C" void kernel_launch(void* const* d_in, const int* in_sizes, int n_in,
                              void* d_out, int out_size)
{
    const int*   skills    = (const int*)  d_in[0];
    const int*   responses = (const int*)  d_in[1];
    const float* k_emb     = (const float*)d_in[2];
    const float* v_emb     = (const float*)d_in[3];
    const float* Mk        = (const float*)d_in[4];
    const float* Mv0       = (const float*)d_in[5];
    const float* e_W       = (const float*)d_in[6];
    const float* e_b       = (const float*)d_in[7];
    const float* a_W       = (const float*)d_in[8];
    const float* a_b       = (const float*)d_in[9];
    const float* f_W       = (const float*)d_in[10];
    const float* f_b       = (const float*)d_in[11];
    const float* p_W       = (const float*)d_in[12];
    const float* p_b       = (const float*)d_in[13];
    float* out = (float*)d_out;

    const size_t SZA = (size_t)(128*132 + 128*136) * sizeof(float);        // 137216
    const size_t SZB = (size_t)(3*L_*64) * sizeof(float);                  // 153600
    const size_t SZC = (size_t)(128*132 + 128*136 + 128 + 256) * sizeof(float); // 138752

    cudaFuncSetAttribute(kA_tables, cudaFuncAttributeMaxDynamicSharedMemorySize, (int)SZA);
    cudaFuncSetAttribute(kB_scan,   cudaFuncAttributeMaxDynamicSharedMemorySize, (int)SZB);
    cudaFuncSetAttribute(kC_out,    cudaFuncAttributeMaxDynamicSharedMemorySize, (int)SZC);

    k0_transpose<<<dim3(16, 4), 256>>>(e_W, a_W, f_W);
    kA_tables<<<56, 512, SZA>>>(k_emb, v_emb, Mk, e_b, a_b, f_b);
    kB_scan<<<dim3(B_, 2), 512, SZB>>>(skills, responses, Mv0);
    kC_out<<<100, 512, SZC>>>(skills, p_W, p_b, out);
}